// round 5
// baseline (speedup 1.0000x reference)
#include <cuda_runtime.h>
#include <math.h>

#define B_   16
#define T_   32
#define L_   64
#define D_   768
#define H_   12
#define HD_  64
#define F_   2048
#define ZD_  100
#define TD3  2304
#define NPAD 512
#define NTOK (NPAD * L_)   // 32768
#define NLAY 2

// ---------------- static device scratch (no allocations allowed) ----------------
__device__ int   g_bidx[NPAD], g_tidx[NPAD], g_nresp[B_], g_node[B_], g_Ntot;
__device__ float g_X  [(size_t)NTOK * D_];    // activations
__device__ float g_EMB[(size_t)NTOK * D_];    // original gathered reply embeddings
__device__ float g_QKV[(size_t)NTOK * TD3];
__device__ float g_ATT[(size_t)NTOK * D_];
__device__ float g_Y  [(size_t)NTOK * D_];
__device__ float g_FF [(size_t)NTOK * F_];
__device__ float g_Z  [(size_t)NTOK * ZD_];
__device__ float g_BIAS[L_ * NPAD];
__device__ float g_S[NPAD];

// ---------------- helpers ----------------
__device__ __forceinline__ float blockReduceSum256(float v) {
    __shared__ float sh[8];
    #pragma unroll
    for (int o = 16; o; o >>= 1) v += __shfl_xor_sync(0xffffffffu, v, o);
    int w = threadIdx.x >> 5;
    if ((threadIdx.x & 31) == 0) sh[w] = v;
    __syncthreads();
    if (threadIdx.x == 0) {
        float t = 0.f;
        #pragma unroll
        for (int i = 0; i < 8; i++) t += sh[i];
        sh[0] = t;
    }
    __syncthreads();
    float r = sh[0];
    __syncthreads();
    return r;
}

// ---------------- setup: packing maps ----------------
__global__ void k_setup(const int* __restrict__ tree_lens) {
    if (threadIdx.x == 0 && blockIdx.x == 0) {
        int p = 0;
        for (int b = 0; b < B_; b++) {
            int nr = tree_lens[b] - 1;
            g_nresp[b] = nr;
            for (int j = 0; j < nr; j++) { g_bidx[p] = b; g_tidx[p] = 1 + j; p++; }
        }
        g_Ntot = p;
        for (int j = p; j < NPAD; j++) { g_bidx[j] = 0; g_tidx[j] = 0; }
    }
}

// ---------------- gather packed replies ----------------
__global__ __launch_bounds__(256) void k_gather(const float* __restrict__ emb) {
    int idx = blockIdx.x * 256 + threadIdx.x;            // < NTOK*D
    int token = idx / D_;
    int d = idx - token * D_;
    int n = token >> 6, l = token & 63;
    float v = 0.f;
    if (n < g_Ntot)
        v = emb[((g_bidx[n] * T_ + g_tidx[n]) * L_ + l) * D_ + d];
    g_EMB[idx] = v;
    g_X[idx] = v;
}

__global__ __launch_bounds__(256) void k_bias(const float* __restrict__ amask) {
    int idx = blockIdx.x * 256 + threadIdx.x;            // < L_*NPAD
    int l = idx >> 9, m = idx & (NPAD - 1);
    float v = -1e30f;
    if (m < g_Ntot)
        v = amask[(g_bidx[m] * T_ + g_tidx[m]) * L_ + l];
    g_BIAS[idx] = v;
}

// ---------------- SGEMM: C[M,N] = A[M,K] @ B[N,K]^T + bias (+Res) (+act) ----------------
// M == NTOK always. act: 0 none, 1 relu, 2 tanh.
__global__ __launch_bounds__(256, 2) void sgemm_k(
    const float* __restrict__ A, const float* __restrict__ Bw,
    const float* __restrict__ bias, const float* __restrict__ Res,
    float* __restrict__ C, int N, int K, int act)
{
    __shared__ float As[8][128];
    __shared__ float Bs[8][128];
    const int bm = blockIdx.y * 128, bn = blockIdx.x * 128;
    const int tid = threadIdx.x;
    const int tr = (tid >> 4) << 3, tc = (tid & 15) << 3;
    const int lrow = tid >> 1, lcol = (tid & 1) << 2;
    float acc[8][8];
    #pragma unroll
    for (int i = 0; i < 8; i++)
        #pragma unroll
        for (int j = 0; j < 8; j++) acc[i][j] = 0.f;

    const float* Ap = A + (size_t)(bm + lrow) * K;
    const float* Bp = Bw + (size_t)(bn + lrow) * K;
    const bool bvalid = (bn + lrow) < N;

    for (int k0 = 0; k0 < K; k0 += 8) {
        int ka = k0 + lcol;
        float4 av = make_float4(0.f, 0.f, 0.f, 0.f);
        float4 bv = make_float4(0.f, 0.f, 0.f, 0.f);
        if (ka + 4 <= K) {
            av = *(const float4*)(Ap + ka);
        } else {
            if (ka     < K) av.x = Ap[ka];
            if (ka + 1 < K) av.y = Ap[ka + 1];
            if (ka + 2 < K) av.z = Ap[ka + 2];
        }
        if (bvalid) {
            if (ka + 4 <= K) {
                bv = *(const float4*)(Bp + ka);
            } else {
                if (ka     < K) bv.x = Bp[ka];
                if (ka + 1 < K) bv.y = Bp[ka + 1];
                if (ka + 2 < K) bv.z = Bp[ka + 2];
            }
        }
        As[lcol + 0][lrow] = av.x; As[lcol + 1][lrow] = av.y;
        As[lcol + 2][lrow] = av.z; As[lcol + 3][lrow] = av.w;
        Bs[lcol + 0][lrow] = bv.x; Bs[lcol + 1][lrow] = bv.y;
        Bs[lcol + 2][lrow] = bv.z; Bs[lcol + 3][lrow] = bv.w;
        __syncthreads();
        #pragma unroll
        for (int kk = 0; kk < 8; kk++) {
            float4 a0 = *(const float4*)&As[kk][tr];
            float4 a1 = *(const float4*)&As[kk][tr + 4];
            float4 b0 = *(const float4*)&Bs[kk][tc];
            float4 b1 = *(const float4*)&Bs[kk][tc + 4];
            float ra[8] = {a0.x, a0.y, a0.z, a0.w, a1.x, a1.y, a1.z, a1.w};
            float rb[8] = {b0.x, b0.y, b0.z, b0.w, b1.x, b1.y, b1.z, b1.w};
            #pragma unroll
            for (int i = 0; i < 8; i++)
                #pragma unroll
                for (int j = 0; j < 8; j++)
                    acc[i][j] += ra[i] * rb[j];
        }
        __syncthreads();
    }

    #pragma unroll
    for (int i = 0; i < 8; i++) {
        int m = bm + tr + i;
        #pragma unroll
        for (int j = 0; j < 8; j++) {
            int n = bn + tc + j;
            if (n < N) {
                float v = acc[i][j] + bias[n];
                if (Res) v += Res[(size_t)m * N + n];
                if (act == 1) v = fmaxf(v, 0.f);
                else if (act == 2) v = tanhf(v);
                C[(size_t)m * N + n] = v;
            }
        }
    }
}

// ---------------- attention over the N (response) dimension ----------------
// grid: (NPAD/64, L_, H_), 256 threads. Online-softmax flash style, fp32.
__global__ __launch_bounds__(256) void attn_k(
    const float* __restrict__ QKV, const float* __restrict__ BIASLM,
    float* __restrict__ O)
{
    const int qt = blockIdx.x, l = blockIdx.y, h = blockIdx.z;
    __shared__ float Qs[64][65];   // [d][m]  (transposed)
    __shared__ float Ks[64][33];   // [d][n]
    __shared__ float Vs[32][65];   // [n][dv]
    __shared__ float Ps[32][65];   // [n][q]
    __shared__ float biass[32];

    const int tid = threadIdx.x;
    const int tq = (tid >> 4) << 2;       // query row base (4 rows)
    const int tk = (tid & 15) << 1;       // key col base (2 cols)
    const int tv = (tid & 15) << 2;       // value col base (4 cols)
    const int n0 = qt * 64;

    for (int idx = tid; idx < 4096; idx += 256) {
        int m = idx >> 6, d = idx & 63;
        Qs[d][m] = QKV[(size_t)((n0 + m) * L_ + l) * TD3 + h * HD_ + d];
    }

    float oacc[4][4];
    #pragma unroll
    for (int i = 0; i < 4; i++)
        #pragma unroll
        for (int j = 0; j < 4; j++) oacc[i][j] = 0.f;
    float rmax[4] = {-INFINITY, -INFINITY, -INFINITY, -INFINITY};
    float rsum[4] = {0.f, 0.f, 0.f, 0.f};

    for (int kc = 0; kc < NPAD; kc += 32) {
        __syncthreads();  // prior PV reads done before overwriting K/V/Ps
        for (int idx = tid; idx < 2048; idx += 256) {
            int n = idx >> 6, d = idx & 63;
            size_t row = (size_t)((kc + n) * L_ + l) * TD3 + h * HD_;
            Ks[d][n] = QKV[row + D_ + d];
            Vs[n][d] = QKV[row + 2 * D_ + d];
        }
        if (tid < 32) biass[tid] = BIASLM[l * NPAD + kc + tid];
        __syncthreads();

        float s[4][2];
        #pragma unroll
        for (int i = 0; i < 4; i++) { s[i][0] = 0.f; s[i][1] = 0.f; }
        #pragma unroll
        for (int d = 0; d < 64; d++) {
            float k0v = Ks[d][tk], k1v = Ks[d][tk + 1];
            #pragma unroll
            for (int i = 0; i < 4; i++) {
                float q = Qs[d][tq + i];
                s[i][0] += q * k0v;
                s[i][1] += q * k1v;
            }
        }
        float scalef[4];
        #pragma unroll
        for (int i = 0; i < 4; i++) {
            float s0 = s[i][0] * 0.125f + biass[tk];
            float s1 = s[i][1] * 0.125f + biass[tk + 1];
            float m = fmaxf(s0, s1);
            #pragma unroll
            for (int o = 1; o < 16; o <<= 1) m = fmaxf(m, __shfl_xor_sync(0xffffffffu, m, o));
            float nm = fmaxf(rmax[i], m);
            float p0 = __expf(s0 - nm);
            float p1 = __expf(s1 - nm);
            float cs = p0 + p1;
            #pragma unroll
            for (int o = 1; o < 16; o <<= 1) cs += __shfl_xor_sync(0xffffffffu, cs, o);
            float sc = __expf(rmax[i] - nm);
            rsum[i] = rsum[i] * sc + cs;
            rmax[i] = nm;
            scalef[i] = sc;
            Ps[tk][tq + i]     = p0;
            Ps[tk + 1][tq + i] = p1;
        }
        __syncthreads();  // Ps visible to all before PV

        #pragma unroll
        for (int i = 0; i < 4; i++)
            #pragma unroll
            for (int j = 0; j < 4; j++) oacc[i][j] *= scalef[i];

        #pragma unroll
        for (int j = 0; j < 32; j++) {
            float v0 = Vs[j][tv], v1 = Vs[j][tv + 1], v2 = Vs[j][tv + 2], v3 = Vs[j][tv + 3];
            #pragma unroll
            for (int i = 0; i < 4; i++) {
                float p = Ps[j][tq + i];
                oacc[i][0] += p * v0;
                oacc[i][1] += p * v1;
                oacc[i][2] += p * v2;
                oacc[i][3] += p * v3;
            }
        }
    }

    #pragma unroll
    for (int i = 0; i < 4; i++) {
        float inv = 1.f / rsum[i];
        size_t base = (size_t)((n0 + tq + i) * L_ + l) * D_ + h * HD_ + tv;
        O[base + 0] = oacc[i][0] * inv;
        O[base + 1] = oacc[i][1] * inv;
        O[base + 2] = oacc[i][2] * inv;
        O[base + 3] = oacc[i][3] * inv;
    }
}

// ---------------- LayerNorm (row of 768), two-pass ----------------
__global__ __launch_bounds__(256) void ln_k(
    const float* __restrict__ Xin, const float* __restrict__ g,
    const float* __restrict__ b, float* __restrict__ Xout)
{
    const size_t base = (size_t)blockIdx.x * D_;
    float v[3];
    #pragma unroll
    for (int c = 0; c < 3; c++) v[c] = Xin[base + c * 256 + threadIdx.x];
    float mean = blockReduceSum256(v[0] + v[1] + v[2]) * (1.f / D_);
    float d2 = 0.f;
    #pragma unroll
    for (int c = 0; c < 3; c++) { float t = v[c] - mean; d2 += t * t; }
    float var = blockReduceSum256(d2) * (1.f / D_);
    float rstd = rsqrtf(var + 1e-5f);
    #pragma unroll
    for (int c = 0; c < 3; c++) {
        int d = c * 256 + threadIdx.x;
        Xout[base + d] = (v[c] - mean) * rstd * g[d] + b[d];
    }
}

// ---------------- scores ----------------
__global__ __launch_bounds__(256) void k_scores() {
    int n = blockIdx.x;
    float local = 0.f;
    #pragma unroll
    for (int c = 0; c < 3; c++) {
        int d = c * 256 + threadIdx.x;
        float sx = 0.f, se = 0.f;
        for (int l = 0; l < L_; l++) {
            size_t r = (size_t)((n << 6) + l) * D_ + d;
            sx += g_X[r];
            se += g_EMB[r];
        }
        float diff = (sx - se) * (1.f / L_);
        local += diff * diff;
    }
    float tot = blockReduceSum256(local);
    if (threadIdx.x == 0) g_S[n] = tot;
}

__global__ void k_select() {
    int b = threadIdx.x;
    if (b < B_) {
        int m = g_nresp[b];
        float best = 3.4e38f;
        int bi = 0;
        for (int j = 0; j < m; j++) {
            float v = g_S[j];
            if (v < best) { best = v; bi = j; }
        }
        g_node[b] = bi;
    }
}

// ---------------- outputs ----------------
__global__ __launch_bounds__(256) void k_out_small(
    const float* __restrict__ amask, float* __restrict__ o_oh,
    float* __restrict__ o_ext, float* __restrict__ o_ntl,
    float* __restrict__ o_msk, float* __restrict__ o_sc)
{
    int idx = blockIdx.x * 256 + threadIdx.x;   // < B*T*L
    int b = idx >> 11, t = (idx >> 6) & 31, l = idx & 63;
    int nd = g_node[b] + 1;
    float ohv = (t == 0 || t == nd) ? 1.f : 0.f;
    o_ext[idx] = ohv;
    float mv = 0.f;
    if (t == 0)      mv = amask[(b * T_ + 0)  * L_ + l];
    else if (t == 1) mv = amask[(b * T_ + nd) * L_ + l];
    o_msk[idx] = mv;
    if (l == 0) o_oh[b * T_ + t] = ohv;
    if (t == 0 && l == 0) o_ntl[b] = 2.0f;
    if (idx == 0 && o_sc) *o_sc = 0.f;
}

__global__ __launch_bounds__(256) void k_out_emb(
    const float* __restrict__ emb, float* __restrict__ o_emb)
{
    int idx = blockIdx.x * 256 + threadIdx.x;   // < B*T*L*D
    const int perB = T_ * L_ * D_;              // 1572864
    const int perT = L_ * D_;                   // 49152
    int b = idx / perB;
    int r = idx - b * perB;
    int t = r / perT;
    int rl = r - t * perT;
    int st = (t == 1) ? (g_node[b] + 1) : 0;
    o_emb[idx] = emb[(size_t)b * perB + (size_t)st * perT + rl];
}

// ---------------- host orchestration ----------------
static void run_gemm(const float* A, const float* Bw, const float* bias,
                     const float* Res, float* C, int N, int K, int act) {
    dim3 grid((N + 127) / 128, NTOK / 128);
    sgemm_k<<<grid, 256>>>(A, Bw, bias, Res, C, N, K, act);
}

static void run_stack(const float* qkv_w, const float* qkv_b,
                      const float* out_w, const float* out_b,
                      const float* g1, const float* b1,
                      const float* w1, const float* c1,
                      const float* w2, const float* c2,
                      const float* g2, const float* b2,
                      float* X, float* EMBunused)
{
    (void)EMBunused;
    for (int i = 0; i < NLAY; i++) {
        run_gemm(X, qkv_w + (size_t)i * TD3 * D_, qkv_b + (size_t)i * TD3,
                 nullptr, g_QKV, TD3, D_, 0);
        attn_k<<<dim3(NPAD / 64, L_, H_), 256>>>(g_QKV, g_BIAS, g_ATT);
        run_gemm(g_ATT, out_w + (size_t)i * D_ * D_, out_b + (size_t)i * D_,
                 X, g_Y, D_, D_, 0);
        ln_k<<<NTOK, 256>>>(g_Y, g1 + (size_t)i * D_, b1 + (size_t)i * D_, X);
        run_gemm(X, w1 + (size_t)i * F_ * D_, c1 + (size_t)i * F_,
                 nullptr, g_FF, F_, D_, 1);
        run_gemm(g_FF, w2 + (size_t)i * D_ * F_, c2 + (size_t)i * D_,
                 X, g_Y, D_, F_, 0);
        ln_k<<<NTOK, 256>>>(g_Y, g2 + (size_t)i * D_, b2 + (size_t)i * D_, X);
    }
}

extern "C" void kernel_launch(void* const* d_in, const int* in_sizes, int n_in,
                              void* d_out, int out_size) {
    const int*   tree_lens = (const int*)d_in[0];
    const float* emb       = (const float*)d_in[1];
    const float* amask     = (const float*)d_in[2];
    const float* ep[12];
    const float* dp[12];
    for (int i = 0; i < 12; i++) ep[i] = (const float*)d_in[3 + i];
    for (int i = 0; i < 12; i++) dp[i] = (const float*)d_in[15 + i];
    const float* pe_w = (const float*)d_in[27];
    const float* pe_b = (const float*)d_in[28];
    const float* pd_w = (const float*)d_in[29];
    const float* pd_b = (const float*)d_in[30];

    float* out = (float*)d_out;
    // output layout: oh[512], ext_mask[32768], (n_ext_adv scalar?), new_tree_lens[16],
    //                new_emb[25165824], new_msk[32768]
    const long long base_total = 512LL + 32768 + 16 + 25165824 + 32768; // 25231888
    int extra = (int)((long long)out_size - base_total);  // 1 if scalar present
    if (extra < 0) extra = 0;
    if (extra > 1) extra = 1;
    float* o_oh  = out;
    float* o_ext = out + 512;
    float* o_sc  = extra ? (out + 512 + 32768) : nullptr;
    float* o_ntl = out + 512 + 32768 + extra;
    float* o_emb = o_ntl + 16;
    float* o_msk = o_emb + (size_t)B_ * T_ * L_ * D_;

    // device-side address of __device__ globals for passing into helper
    float* Xp;   cudaGetSymbolAddress((void**)&Xp, g_X);

    k_setup<<<1, 32>>>(tree_lens);
    k_gather<<<(NTOK * D_) / 256, 256>>>(emb);
    k_bias<<<(L_ * NPAD) / 256, 256>>>(amask);

    // encoder stack
    run_stack(ep[0], ep[1], ep[2], ep[3], ep[4], ep[5],
              ep[6], ep[7], ep[8], ep[9], ep[10], ep[11], Xp, nullptr);

    // bottleneck: z = tanh(h @ pe_w^T + pe_b); zd = tanh(z @ pd_w^T + pd_b)
    float* Zp; cudaGetSymbolAddress((void**)&Zp, g_Z);
    run_gemm(Xp, pe_w, pe_b, nullptr, Zp, ZD_, D_, 2);
    run_gemm(Zp, pd_w, pd_b, nullptr, Xp, D_, ZD_, 2);

    // decoder stack
    run_stack(dp[0], dp[1], dp[2], dp[3], dp[4], dp[5],
              dp[6], dp[7], dp[8], dp[9], dp[10], dp[11], Xp, nullptr);

    k_scores<<<64, 256>>>();
    k_select<<<1, 32>>>();
    k_out_small<<<(B_ * T_ * L_) / 256, 256>>>(amask, o_oh, o_ext, o_ntl, o_msk, o_sc);
    k_out_emb<<<(B_ * T_ * L_ * D_) / 256, 256>>>(emb, o_emb);

    (void)in_sizes; (void)n_in;
}

// round 13
// speedup vs baseline: 2.1624x; 2.1624x over previous
#include <cuda_runtime.h>
#include <cuda_bf16.h>
#include <math.h>
#include <stdint.h>

#define B_   16
#define T_   32
#define L_   64
#define D_   768
#define H_   12
#define HD_  64
#define F_   2048
#define ZD_  100
#define TD3  2304
#define NPAD 512
#define NTOK (NPAD * L_)   // 32768
#define NLAY 2

// ---------------- static device scratch (no allocations allowed) ----------------
__device__ int   g_bidx[NPAD], g_tidx[NPAD], g_nresp[B_], g_node[B_], g_Ntot;
__device__ float g_X  [(size_t)NTOK * D_];
__device__ float g_EMB[(size_t)NTOK * D_];
__device__ float g_QKV[(size_t)NTOK * TD3];
__device__ float g_ATT[(size_t)NTOK * D_];
__device__ float g_Y  [(size_t)NTOK * D_];
__device__ float g_FF [(size_t)NTOK * F_];
__device__ float g_Z  [(size_t)NTOK * ZD_];
__device__ float g_BIAS[L_ * NPAD];
__device__ float g_S[NPAD];

// ================= baseline (family-safe) tensor-core helpers =================
__device__ __forceinline__ uint32_t smem_to_u32(const void* p) {
    uint32_t a;
    asm("{ .reg .u64 t; cvta.to.shared.u64 t, %1; cvt.u32.u64 %0, t; }" : "=r"(a) : "l"(p));
    return a;
}
__device__ __forceinline__ void ldsm4(uint32_t* r, uint32_t addr) {
    asm volatile("ldmatrix.sync.aligned.m8n8.x4.shared.b16 {%0,%1,%2,%3}, [%4];"
                 : "=r"(r[0]), "=r"(r[1]), "=r"(r[2]), "=r"(r[3]) : "r"(addr));
}
__device__ __forceinline__ void mma_bf16(float* c, const uint32_t* a,
                                         uint32_t b0, uint32_t b1) {
    asm volatile(
        "mma.sync.aligned.m16n8k16.row.col.f32.bf16.bf16.f32 "
        "{%0,%1,%2,%3}, {%4,%5,%6,%7}, {%8,%9}, {%0,%1,%2,%3};"
        : "+f"(c[0]), "+f"(c[1]), "+f"(c[2]), "+f"(c[3])
        : "r"(a[0]), "r"(a[1]), "r"(a[2]), "r"(a[3]), "r"(b0), "r"(b1));
}

// GEMM tiling: 128x128 CTA tile, K chunks of 64. 8 warps (2 M x 4 N), warp = 64x32.
// Smem: bf16 tiles with padded rows of 72 elems (144 B) -> conflict-free ldmatrix.
#define GBK   64
#define SPAD  72
#define SROWB (SPAD * 2)            // 144 bytes per padded row
#define SM_AH 0
#define SM_AL 18432                 // 128*144
#define SM_BH 36864
#define SM_BL 55296
#define SM_TOT 73728

// ---------------- split-bf16 HMMA GEMM ----------------
// C[M,N] = A[M,K] @ B[N,K]^T + bias (+Res) (+act). M == NTOK. act: 0 none, 1 relu, 2 tanh.
// A = Ah + Al, B = Bh + Bl (bf16 hi/lo); acc += AhBh + AhBl + AlBh in fp32.
__global__ __launch_bounds__(256, 2) void gemm_mma(
    const float* __restrict__ A, const float* __restrict__ Bw,
    const float* __restrict__ bias, const float* __restrict__ Res,
    float* __restrict__ C, int N, int K, int act)
{
    extern __shared__ char smem[];
    const uint32_t sb = smem_to_u32(smem);
    const int tid = threadIdx.x;
    const int lane = tid & 31, wid = tid >> 5;
    const int wmB = (wid >> 2) * 64;      // warp M offset within tile
    const int wnB = (wid & 3) * 32;       // warp N offset within tile
    const int bm = blockIdx.y * 128, bn = blockIdx.x * 128;

    float acc[4][4][4];
    #pragma unroll
    for (int i = 0; i < 4; i++)
        #pragma unroll
        for (int j = 0; j < 4; j++)
            #pragma unroll
            for (int r = 0; r < 4; r++) acc[i][j][r] = 0.f;

    // ldmatrix per-lane address pieces (shared by A and B tiles)
    const int lrow16 = lane & 15;                 // row within 16-row block
    const int lk8    = ((lane >> 4) & 1) << 3;    // k-offset 0 or 8

    const int nchunks = (K + GBK - 1) / GBK;
    for (int ch = 0; ch < nchunks; ch++) {
        const int k0 = ch * GBK;
        __syncthreads();   // previous chunk's MMAs read smem before overwrite
        // ---- fill: load fp32, split into bf16 hi/lo, store padded rows ----
        #pragma unroll
        for (int it = 0; it < 8; it++) {
            const int idx = it * 256 + tid;       // 0..2047
            const int row = idx >> 4;             // 0..127
            const int q   = idx & 15;             // float4 slot (k = q*4)
            const int kk  = k0 + (q << 2);
            const bool kval = (kk + 4 <= K);
            const uint32_t off = (uint32_t)row * SROWB + (uint32_t)(q << 3);

            float4 av = make_float4(0.f, 0.f, 0.f, 0.f);
            if (kval) av = *(const float4*)(A + (size_t)(bm + row) * K + kk);
            {
                __nv_bfloat16 h0 = __float2bfloat16(av.x), h1 = __float2bfloat16(av.y);
                __nv_bfloat16 h2 = __float2bfloat16(av.z), h3 = __float2bfloat16(av.w);
                __nv_bfloat16 l0 = __float2bfloat16(av.x - __bfloat162float(h0));
                __nv_bfloat16 l1 = __float2bfloat16(av.y - __bfloat162float(h1));
                __nv_bfloat16 l2 = __float2bfloat16(av.z - __bfloat162float(h2));
                __nv_bfloat16 l3 = __float2bfloat16(av.w - __bfloat162float(h3));
                uint32_t h01 = (uint32_t)__bfloat16_as_ushort(h0) | ((uint32_t)__bfloat16_as_ushort(h1) << 16);
                uint32_t h23 = (uint32_t)__bfloat16_as_ushort(h2) | ((uint32_t)__bfloat16_as_ushort(h3) << 16);
                uint32_t l01 = (uint32_t)__bfloat16_as_ushort(l0) | ((uint32_t)__bfloat16_as_ushort(l1) << 16);
                uint32_t l23 = (uint32_t)__bfloat16_as_ushort(l2) | ((uint32_t)__bfloat16_as_ushort(l3) << 16);
                *(uint2*)(smem + SM_AH + off) = make_uint2(h01, h23);
                *(uint2*)(smem + SM_AL + off) = make_uint2(l01, l23);
            }
            float4 bv = make_float4(0.f, 0.f, 0.f, 0.f);
            if (kval && (bn + row) < N)
                bv = *(const float4*)(Bw + (size_t)(bn + row) * K + kk);
            {
                __nv_bfloat16 h0 = __float2bfloat16(bv.x), h1 = __float2bfloat16(bv.y);
                __nv_bfloat16 h2 = __float2bfloat16(bv.z), h3 = __float2bfloat16(bv.w);
                __nv_bfloat16 l0 = __float2bfloat16(bv.x - __bfloat162float(h0));
                __nv_bfloat16 l1 = __float2bfloat16(bv.y - __bfloat162float(h1));
                __nv_bfloat16 l2 = __float2bfloat16(bv.z - __bfloat162float(h2));
                __nv_bfloat16 l3 = __float2bfloat16(bv.w - __bfloat162float(h3));
                uint32_t h01 = (uint32_t)__bfloat16_as_ushort(h0) | ((uint32_t)__bfloat16_as_ushort(h1) << 16);
                uint32_t h23 = (uint32_t)__bfloat16_as_ushort(h2) | ((uint32_t)__bfloat16_as_ushort(h3) << 16);
                uint32_t l01 = (uint32_t)__bfloat16_as_ushort(l0) | ((uint32_t)__bfloat16_as_ushort(l1) << 16);
                uint32_t l23 = (uint32_t)__bfloat16_as_ushort(l2) | ((uint32_t)__bfloat16_as_ushort(l3) << 16);
                *(uint2*)(smem + SM_BH + off) = make_uint2(h01, h23);
                *(uint2*)(smem + SM_BL + off) = make_uint2(l01, l23);
            }
        }
        __syncthreads();

        // ---- compute: 4 k16 steps ----
        #pragma unroll
        for (int ks = 0; ks < 4; ks++) {
            const uint32_t koffB = (uint32_t)((ks * 16 + lk8) * 2);
            // B fragments for this warp's 32 N-columns: two n16 ldmatrix.x4 loads
            uint32_t bh[2][4], bl[2][4];
            #pragma unroll
            for (int j = 0; j < 2; j++) {
                uint32_t baddr = sb + SM_BH +
                    (uint32_t)(wnB + j * 16 + lrow16) * SROWB + koffB;
                ldsm4(bh[j], baddr);
                ldsm4(bl[j], baddr + (SM_BL - SM_BH));
            }
            #pragma unroll
            for (int mi = 0; mi < 4; mi++) {
                uint32_t ah[4], al[4];
                uint32_t aaddr = sb + SM_AH +
                    (uint32_t)(wmB + mi * 16 + lrow16) * SROWB + koffB;
                ldsm4(ah, aaddr);
                ldsm4(al, aaddr + (SM_AL - SM_AH));
                #pragma unroll
                for (int nj = 0; nj < 4; nj++) {
                    const int j = nj >> 1, p = nj & 1;
                    const uint32_t b0h = bh[j][p], b1h = bh[j][2 + p];
                    const uint32_t b0l = bl[j][p], b1l = bl[j][2 + p];
                    mma_bf16(acc[mi][nj], ah, b0h, b1h);   // Ah*Bh
                    mma_bf16(acc[mi][nj], ah, b0l, b1l);   // Ah*Bl
                    mma_bf16(acc[mi][nj], al, b0h, b1h);   // Al*Bh
                }
            }
        }
    }

    // ---- epilogue: fused bias / residual / activation ----
    const int r0 = bm + wmB + (lane >> 2);
    #pragma unroll
    for (int mi = 0; mi < 4; mi++) {
        #pragma unroll
        for (int half = 0; half < 2; half++) {
            const int m = r0 + mi * 16 + half * 8;
            const size_t crow = (size_t)m * N;
            #pragma unroll
            for (int nj = 0; nj < 4; nj++) {
                const int n = bn + wnB + nj * 8 + ((lane & 3) << 1);
                if (n + 2 <= N) {
                    float2 v;
                    v.x = acc[mi][nj][half * 2 + 0] + bias[n];
                    v.y = acc[mi][nj][half * 2 + 1] + bias[n + 1];
                    if (Res) {
                        float2 rr = *(const float2*)(Res + crow + n);
                        v.x += rr.x; v.y += rr.y;
                    }
                    if (act == 1) { v.x = fmaxf(v.x, 0.f); v.y = fmaxf(v.y, 0.f); }
                    else if (act == 2) { v.x = tanhf(v.x); v.y = tanhf(v.y); }
                    *(float2*)(C + crow + n) = v;
                } else {
                    #pragma unroll
                    for (int e = 0; e < 2; e++) {
                        const int ne = n + e;
                        if (ne < N) {
                            float v = acc[mi][nj][half * 2 + e] + bias[ne];
                            if (Res) v += Res[crow + ne];
                            if (act == 1) v = fmaxf(v, 0.f);
                            else if (act == 2) v = tanhf(v);
                            C[crow + ne] = v;
                        }
                    }
                }
            }
        }
    }
}

// ---------------- helpers ----------------
__device__ __forceinline__ float blockReduceSum256(float v) {
    __shared__ float sh[8];
    #pragma unroll
    for (int o = 16; o; o >>= 1) v += __shfl_xor_sync(0xffffffffu, v, o);
    int w = threadIdx.x >> 5;
    if ((threadIdx.x & 31) == 0) sh[w] = v;
    __syncthreads();
    if (threadIdx.x == 0) {
        float t = 0.f;
        #pragma unroll
        for (int i = 0; i < 8; i++) t += sh[i];
        sh[0] = t;
    }
    __syncthreads();
    float r = sh[0];
    __syncthreads();
    return r;
}

// ---------------- setup: packing maps ----------------
__global__ void k_setup(const int* __restrict__ tree_lens) {
    if (threadIdx.x == 0 && blockIdx.x == 0) {
        int p = 0;
        for (int b = 0; b < B_; b++) {
            int nr = tree_lens[b] - 1;
            g_nresp[b] = nr;
            for (int j = 0; j < nr; j++) { g_bidx[p] = b; g_tidx[p] = 1 + j; p++; }
        }
        g_Ntot = p;
        for (int j = p; j < NPAD; j++) { g_bidx[j] = 0; g_tidx[j] = 0; }
    }
}

__global__ __launch_bounds__(256) void k_gather(const float* __restrict__ emb) {
    int idx = blockIdx.x * 256 + threadIdx.x;
    int token = idx / D_;
    int d = idx - token * D_;
    int n = token >> 6, l = token & 63;
    float v = 0.f;
    if (n < g_Ntot)
        v = emb[((g_bidx[n] * T_ + g_tidx[n]) * L_ + l) * D_ + d];
    g_EMB[idx] = v;
    g_X[idx] = v;
}

__global__ __launch_bounds__(256) void k_bias(const float* __restrict__ amask) {
    int idx = blockIdx.x * 256 + threadIdx.x;
    int l = idx >> 9, m = idx & (NPAD - 1);
    float v = -1e30f;
    if (m < g_Ntot)
        v = amask[(g_bidx[m] * T_ + g_tidx[m]) * L_ + l];
    g_BIAS[idx] = v;
}

// ---------------- attention (fp32 flash over N dimension) ----------------
__global__ __launch_bounds__(256) void attn_k(
    const float* __restrict__ QKV, const float* __restrict__ BIASLM,
    float* __restrict__ O)
{
    const int qt = blockIdx.x, l = blockIdx.y, h = blockIdx.z;
    __shared__ float Qs[64][65];
    __shared__ float Ks[64][33];
    __shared__ float Vs[32][65];
    __shared__ float Ps[32][65];
    __shared__ float biass[32];

    const int tid = threadIdx.x;
    const int tq = (tid >> 4) << 2;
    const int tk = (tid & 15) << 1;
    const int tv = (tid & 15) << 2;
    const int n0 = qt * 64;

    for (int idx = tid; idx < 4096; idx += 256) {
        int m = idx >> 6, d = idx & 63;
        Qs[d][m] = QKV[(size_t)((n0 + m) * L_ + l) * TD3 + h * HD_ + d];
    }

    float oacc[4][4];
    #pragma unroll
    for (int i = 0; i < 4; i++)
        #pragma unroll
        for (int j = 0; j < 4; j++) oacc[i][j] = 0.f;
    float rmax[4] = {-INFINITY, -INFINITY, -INFINITY, -INFINITY};
    float rsum[4] = {0.f, 0.f, 0.f, 0.f};

    for (int kc = 0; kc < NPAD; kc += 32) {
        __syncthreads();
        for (int idx = tid; idx < 2048; idx += 256) {
            int n = idx >> 6, d = idx & 63;
            size_t row = (size_t)((kc + n) * L_ + l) * TD3 + h * HD_;
            Ks[d][n] = QKV[row + D_ + d];
            Vs[n][d] = QKV[row + 2 * D_ + d];
        }
        if (tid < 32) biass[tid] = BIASLM[l * NPAD + kc + tid];
        __syncthreads();

        float s[4][2];
        #pragma unroll
        for (int i = 0; i < 4; i++) { s[i][0] = 0.f; s[i][1] = 0.f; }
        #pragma unroll
        for (int d = 0; d < 64; d++) {
            float k0v = Ks[d][tk], k1v = Ks[d][tk + 1];
            #pragma unroll
            for (int i = 0; i < 4; i++) {
                float q = Qs[d][tq + i];
                s[i][0] += q * k0v;
                s[i][1] += q * k1v;
            }
        }
        float scalef[4];
        #pragma unroll
        for (int i = 0; i < 4; i++) {
            float s0 = s[i][0] * 0.125f + biass[tk];
            float s1 = s[i][1] * 0.125f + biass[tk + 1];
            float m = fmaxf(s0, s1);
            #pragma unroll
            for (int o = 1; o < 16; o <<= 1) m = fmaxf(m, __shfl_xor_sync(0xffffffffu, m, o));
            float nm = fmaxf(rmax[i], m);
            float p0 = __expf(s0 - nm);
            float p1 = __expf(s1 - nm);
            float cs = p0 + p1;
            #pragma unroll
            for (int o = 1; o < 16; o <<= 1) cs += __shfl_xor_sync(0xffffffffu, cs, o);
            float sc = __expf(rmax[i] - nm);
            rsum[i] = rsum[i] * sc + cs;
            rmax[i] = nm;
            scalef[i] = sc;
            Ps[tk][tq + i]     = p0;
            Ps[tk + 1][tq + i] = p1;
        }
        __syncthreads();

        #pragma unroll
        for (int i = 0; i < 4; i++)
            #pragma unroll
            for (int j = 0; j < 4; j++) oacc[i][j] *= scalef[i];

        #pragma unroll
        for (int j = 0; j < 32; j++) {
            float v0 = Vs[j][tv], v1 = Vs[j][tv + 1], v2 = Vs[j][tv + 2], v3 = Vs[j][tv + 3];
            #pragma unroll
            for (int i = 0; i < 4; i++) {
                float p = Ps[j][tq + i];
                oacc[i][0] += p * v0;
                oacc[i][1] += p * v1;
                oacc[i][2] += p * v2;
                oacc[i][3] += p * v3;
            }
        }
    }

    #pragma unroll
    for (int i = 0; i < 4; i++) {
        float inv = 1.f / rsum[i];
        size_t base = (size_t)((n0 + tq + i) * L_ + l) * D_ + h * HD_ + tv;
        O[base + 0] = oacc[i][0] * inv;
        O[base + 1] = oacc[i][1] * inv;
        O[base + 2] = oacc[i][2] * inv;
        O[base + 3] = oacc[i][3] * inv;
    }
}

// ---------------- LayerNorm ----------------
__global__ __launch_bounds__(256) void ln_k(
    const float* __restrict__ Xin, const float* __restrict__ g,
    const float* __restrict__ b, float* __restrict__ Xout)
{
    const size_t base = (size_t)blockIdx.x * D_;
    float v[3];
    #pragma unroll
    for (int c = 0; c < 3; c++) v[c] = Xin[base + c * 256 + threadIdx.x];
    float mean = blockReduceSum256(v[0] + v[1] + v[2]) * (1.f / D_);
    float d2 = 0.f;
    #pragma unroll
    for (int c = 0; c < 3; c++) { float t = v[c] - mean; d2 += t * t; }
    float var = blockReduceSum256(d2) * (1.f / D_);
    float rstd = rsqrtf(var + 1e-5f);
    #pragma unroll
    for (int c = 0; c < 3; c++) {
        int d = c * 256 + threadIdx.x;
        Xout[base + d] = (v[c] - mean) * rstd * g[d] + b[d];
    }
}

// ---------------- scores / select / outputs ----------------
__global__ __launch_bounds__(256) void k_scores() {
    int n = blockIdx.x;
    float local = 0.f;
    #pragma unroll
    for (int c = 0; c < 3; c++) {
        int d = c * 256 + threadIdx.x;
        float sx = 0.f, se = 0.f;
        for (int l = 0; l < L_; l++) {
            size_t r = (size_t)((n << 6) + l) * D_ + d;
            sx += g_X[r];
            se += g_EMB[r];
        }
        float diff = (sx - se) * (1.f / L_);
        local += diff * diff;
    }
    float tot = blockReduceSum256(local);
    if (threadIdx.x == 0) g_S[n] = tot;
}

__global__ void k_select() {
    int b = threadIdx.x;
    if (b < B_) {
        int m = g_nresp[b];
        float best = 3.4e38f;
        int bi = 0;
        for (int j = 0; j < m; j++) {
            float v = g_S[j];
            if (v < best) { best = v; bi = j; }
        }
        g_node[b] = bi;
    }
}

__global__ __launch_bounds__(256) void k_out_small(
    const float* __restrict__ amask, float* __restrict__ o_oh,
    float* __restrict__ o_ext, float* __restrict__ o_ntl,
    float* __restrict__ o_msk, float* __restrict__ o_sc)
{
    int idx = blockIdx.x * 256 + threadIdx.x;
    int b = idx >> 11, t = (idx >> 6) & 31, l = idx & 63;
    int nd = g_node[b] + 1;
    float ohv = (t == 0 || t == nd) ? 1.f : 0.f;
    o_ext[idx] = ohv;
    float mv = 0.f;
    if (t == 0)      mv = amask[(b * T_ + 0)  * L_ + l];
    else if (t == 1) mv = amask[(b * T_ + nd) * L_ + l];
    o_msk[idx] = mv;
    if (l == 0) o_oh[b * T_ + t] = ohv;
    if (t == 0 && l == 0) o_ntl[b] = 2.0f;
    if (idx == 0 && o_sc) *o_sc = 0.f;
}

__global__ __launch_bounds__(256) void k_out_emb(
    const float* __restrict__ emb, float* __restrict__ o_emb)
{
    int idx = blockIdx.x * 256 + threadIdx.x;
    const int perB = T_ * L_ * D_;
    const int perT = L_ * D_;
    int b = idx / perB;
    int r = idx - b * perB;
    int t = r / perT;
    int rl = r - t * perT;
    int st = (t == 1) ? (g_node[b] + 1) : 0;
    o_emb[idx] = emb[(size_t)b * perB + (size_t)st * perT + rl];
}

// ---------------- host orchestration ----------------
static void run_gemm(const float* A, const float* Bw, const float* bias,
                     const float* Res, float* C, int N, int K, int act) {
    dim3 grid((N + 127) / 128, NTOK / 128);
    gemm_mma<<<grid, 256, SM_TOT>>>(A, Bw, bias, Res, C, N, K, act);
}

static void run_stack(const float* qkv_w, const float* qkv_b,
                      const float* out_w, const float* out_b,
                      const float* g1, const float* b1,
                      const float* w1, const float* c1,
                      const float* w2, const float* c2,
                      const float* g2, const float* b2,
                      float* X)
{
    for (int i = 0; i < NLAY; i++) {
        run_gemm(X, qkv_w + (size_t)i * TD3 * D_, qkv_b + (size_t)i * TD3,
                 nullptr, g_QKV, TD3, D_, 0);
        attn_k<<<dim3(NPAD / 64, L_, H_), 256>>>(g_QKV, g_BIAS, g_ATT);
        run_gemm(g_ATT, out_w + (size_t)i * D_ * D_, out_b + (size_t)i * D_,
                 X, g_Y, D_, D_, 0);
        ln_k<<<NTOK, 256>>>(g_Y, g1 + (size_t)i * D_, b1 + (size_t)i * D_, X);
        run_gemm(X, w1 + (size_t)i * F_ * D_, c1 + (size_t)i * F_,
                 nullptr, g_FF, F_, D_, 1);
        run_gemm(g_FF, w2 + (size_t)i * D_ * F_, c2 + (size_t)i * D_,
                 X, g_Y, D_, F_, 0);
        ln_k<<<NTOK, 256>>>(g_Y, g2 + (size_t)i * D_, b2 + (size_t)i * D_, X);
    }
}

extern "C" void kernel_launch(void* const* d_in, const int* in_sizes, int n_in,
                              void* d_out, int out_size) {
    const int*   tree_lens = (const int*)d_in[0];
    const float* emb       = (const float*)d_in[1];
    const float* amask     = (const float*)d_in[2];
    const float* ep[12];
    const float* dp[12];
    for (int i = 0; i < 12; i++) ep[i] = (const float*)d_in[3 + i];
    for (int i = 0; i < 12; i++) dp[i] = (const float*)d_in[15 + i];
    const float* pe_w = (const float*)d_in[27];
    const float* pe_b = (const float*)d_in[28];
    const float* pd_w = (const float*)d_in[29];
    const float* pd_b = (const float*)d_in[30];

    cudaFuncSetAttribute(gemm_mma, cudaFuncAttributeMaxDynamicSharedMemorySize, SM_TOT);

    float* out = (float*)d_out;
    const long long base_total = 512LL + 32768 + 16 + 25165824 + 32768;
    int extra = (int)((long long)out_size - base_total);
    if (extra < 0) extra = 0;
    if (extra > 1) extra = 1;
    float* o_oh  = out;
    float* o_ext = out + 512;
    float* o_sc  = extra ? (out + 512 + 32768) : nullptr;
    float* o_ntl = out + 512 + 32768 + extra;
    float* o_emb = o_ntl + 16;
    float* o_msk = o_emb + (size_t)B_ * T_ * L_ * D_;

    float* Xp;   cudaGetSymbolAddress((void**)&Xp, g_X);
    float* Zp;   cudaGetSymbolAddress((void**)&Zp, g_Z);

    k_setup<<<1, 32>>>(tree_lens);
    k_gather<<<(NTOK * D_) / 256, 256>>>(emb);
    k_bias<<<(L_ * NPAD) / 256, 256>>>(amask);

    run_stack(ep[0], ep[1], ep[2], ep[3], ep[4], ep[5],
              ep[6], ep[7], ep[8], ep[9], ep[10], ep[11], Xp);

    run_gemm(Xp, pe_w, pe_b, nullptr, Zp, ZD_, D_, 2);
    run_gemm(Zp, pd_w, pd_b, nullptr, Xp, D_, ZD_, 2);

    run_stack(dp[0], dp[1], dp[2], dp[3], dp[4], dp[5],
              dp[6], dp[7], dp[8], dp[9], dp[10], dp[11], Xp);

    k_scores<<<64, 256>>>();
    k_select<<<1, 32>>>();
    k_out_small<<<(B_ * T_ * L_) / 256, 256>>>(amask, o_oh, o_ext, o_ntl, o_msk, o_sc);
    k_out_emb<<<(B_ * T_ * L_ * D_) / 256, 256>>>(emb, o_emb);

    (void)in_sizes; (void)n_in;
}